// round 1
// baseline (speedup 1.0000x reference)
#include <cuda_runtime.h>
#include <math.h>

#define NSEQ 1024
#define DMODEL 512
#define NH 8
#define DK 64
#define JT 16

// scratch (no cudaMalloc allowed)
__device__ float g_q[NSEQ * DMODEL];
__device__ float g_k[NSEQ * DMODEL];
__device__ float g_v[NSEQ * DMODEL];
__device__ float g_attn[NSEQ * DMODEL];

// ---------------------------------------------------------------------------
// Generic tiled GEMM: C[M,N] = A[M,K] @ B[K,N] + bias (optional relu)
// 64x64 tile, BK=16, 256 threads, 4x4 per thread.
// ---------------------------------------------------------------------------
__global__ void __launch_bounds__(256) gemm_bias(
    const float* __restrict__ A, const float* __restrict__ B,
    const float* __restrict__ bias, float* __restrict__ C,
    int M, int K, int N, int relu)
{
    __shared__ float As[16][65];
    __shared__ float Bs[16][64];
    const int bm = blockIdx.y * 64;
    const int bn = blockIdx.x * 64;
    const int tid = threadIdx.x;
    const int tx = tid & 15;
    const int ty = tid >> 4;
    float acc[4][4] = {};

    for (int k0 = 0; k0 < K; k0 += 16) {
        {   // A tile: 64 rows x 16 cols, transpose into As[c][r]
            int q = tid * 4;
            int r = q >> 4;
            int c = q & 15;
            float4 av = *(const float4*)(A + (size_t)(bm + r) * K + k0 + c);
            As[c + 0][r] = av.x; As[c + 1][r] = av.y;
            As[c + 2][r] = av.z; As[c + 3][r] = av.w;
        }
        {   // B tile: 16 rows x 64 cols
            int q = tid * 4;
            int r = q >> 6;
            int c = q & 63;
            *(float4*)&Bs[r][c] = *(const float4*)(B + (size_t)(k0 + r) * N + bn + c);
        }
        __syncthreads();
        #pragma unroll
        for (int kk = 0; kk < 16; kk++) {
            float a[4], b[4];
            #pragma unroll
            for (int u = 0; u < 4; u++) a[u] = As[kk][ty * 4 + u];
            #pragma unroll
            for (int u = 0; u < 4; u++) b[u] = Bs[kk][tx * 4 + u];
            #pragma unroll
            for (int r = 0; r < 4; r++)
                #pragma unroll
                for (int c = 0; c < 4; c++)
                    acc[r][c] += a[r] * b[c];
        }
        __syncthreads();
    }
    #pragma unroll
    for (int r = 0; r < 4; r++) {
        int row = bm + ty * 4 + r;
        #pragma unroll
        for (int c = 0; c < 4; c++) {
            int col = bn + tx * 4 + c;
            float v = acc[r][c] + bias[col];
            if (relu) v = fmaxf(v, 0.0f);
            C[(size_t)row * N + col] = v;
        }
    }
}

// ---------------------------------------------------------------------------
// Fused structure-biased attention. One CTA per query row i, 256 threads.
// Online (flash) softmax over j; structure read exactly once; sk/sv computed
// in SMEM per 16-wide j tile.  score = q . (k + sk) * 1/sqrt(dk)
// out[i,h,:] = sum_j p[h,j] * (v[j,h,:] + sv[i,j,:])
// ---------------------------------------------------------------------------
__global__ void __launch_bounds__(256) attn_fused(
    const float* __restrict__ S,     // structure [N, N, 64]
    const float* __restrict__ Wsk, const float* __restrict__ bsk,
    const float* __restrict__ Wsv, const float* __restrict__ bsv,
    float* __restrict__ attn_out)
{
    __shared__ float sW2[64 * 128];     // [e][dd]: dd<64 -> Wsk, dd>=64 -> Wsv
    __shared__ float sB2[128];          // bsk | bsv
    __shared__ float sq[NH * DK];       // q row i
    __shared__ float sE[JT * 64];       // structure tile
    __shared__ float sSKSV[JT * 128];   // [j][dd]: sk | sv
    __shared__ float sS[NH * JT];       // scores -> probs

    const int i    = blockIdx.x;
    const int tid  = threadIdx.x;
    const int lane = tid & 31;
    const int w    = tid >> 5;          // warp id == head id for softmax/acc

    // prologue: stage weights, biases, q row
    for (int idx = tid; idx < 64 * 16; idx += 256) {
        int e = idx >> 4, c4 = idx & 15;
        ((float4*)sW2)[e * 32 + c4]      = ((const float4*)Wsk)[idx];
        ((float4*)sW2)[e * 32 + 16 + c4] = ((const float4*)Wsv)[idx];
    }
    if (tid < 32)
        ((float4*)sB2)[tid] = (tid < 16) ? ((const float4*)bsk)[tid]
                                         : ((const float4*)bsv)[tid - 16];
    if (tid < 128)
        ((float4*)sq)[tid] = ((const float4*)(g_q + (size_t)i * DMODEL))[tid];

    float m_h = -1e30f, l_h = 0.0f;
    float acc0 = 0.0f, acc1 = 0.0f;
    const int d0 = lane * 2;

    const float4* Sbase = (const float4*)(S + (size_t)i * NSEQ * 64);

    for (int j0 = 0; j0 < NSEQ; j0 += JT) {
        __syncthreads();   // protect sE/sSKSV/sS from previous iteration readers
        // ---- load structure tile: JT*64 floats = 256 float4, one per thread
        ((float4*)sE)[tid] = Sbase[(size_t)j0 * 16 + tid];
        __syncthreads();

        // ---- edge projections: sk=relu(E@Wsk+b), sv=E@Wsv+b  (2048 outputs, 8/thread)
        {
            int j   = tid >> 4;
            int dd0 = (tid & 15) * 8;
            float a[8] = {};
            const float* Ej = sE + j * 64;
            #pragma unroll 8
            for (int e = 0; e < 64; e++) {
                float ev = Ej[e];
                const float* wr = sW2 + e * 128 + dd0;
                #pragma unroll
                for (int u = 0; u < 8; u++) a[u] += ev * wr[u];
            }
            float* outp = sSKSV + j * 128 + dd0;
            if (dd0 < 64) {
                #pragma unroll
                for (int u = 0; u < 8; u++) outp[u] = fmaxf(a[u] + sB2[dd0 + u], 0.0f);
            } else {
                #pragma unroll
                for (int u = 0; u < 8; u++) outp[u] = a[u] + sB2[dd0 + u];
            }
        }
        __syncthreads();

        // ---- scores: s[h][j] = q[h] . (k[j,h] + sk[j]) * 0.125
        if (tid < 128) {
            int j = tid >> 3;
            int h = tid & 7;
            const float4* kp  = (const float4*)(g_k + (size_t)(j0 + j) * DMODEL + h * 64);
            const float4* qp  = (const float4*)(sq + h * 64);
            const float4* skp = (const float4*)(sSKSV + j * 128);
            float s = 0.0f;
            #pragma unroll
            for (int u = 0; u < 16; u++) {
                float4 kv = kp[u];
                float4 qv = qp[u];
                float4 sk = skp[u];
                s += qv.x * (kv.x + sk.x) + qv.y * (kv.y + sk.y)
                   + qv.z * (kv.z + sk.z) + qv.w * (kv.w + sk.w);
            }
            sS[h * JT + j] = s * 0.125f;
        }
        __syncthreads();

        // ---- online softmax + accumulate (warp w owns head w)
        {
            float val = (lane < JT) ? sS[w * JT + lane] : -1e30f;
            float mx = val;
            #pragma unroll
            for (int o = 16; o > 0; o >>= 1)
                mx = fmaxf(mx, __shfl_xor_sync(0xffffffffu, mx, o));
            float m_new = fmaxf(m_h, mx);
            float fac = __expf(m_h - m_new);
            float p = (lane < JT) ? __expf(val - m_new) : 0.0f;
            float ps = p;
            #pragma unroll
            for (int o = 16; o > 0; o >>= 1)
                ps += __shfl_xor_sync(0xffffffffu, ps, o);
            l_h = l_h * fac + ps;
            m_h = m_new;
            if (lane < JT) sS[w * JT + lane] = p;
            __syncwarp();

            acc0 *= fac; acc1 *= fac;
            const float* vb = g_v + (size_t)j0 * DMODEL + w * 64 + d0;
            #pragma unroll 4
            for (int j = 0; j < JT; j++) {
                float pj = sS[w * JT + j];
                float2 vv = *(const float2*)(vb + (size_t)j * DMODEL);
                float2 sv = *(const float2*)(sSKSV + j * 128 + 64 + d0);
                acc0 += pj * (vv.x + sv.x);
                acc1 += pj * (vv.y + sv.y);
            }
        }
    }

    float invl = 1.0f / l_h;
    attn_out[(size_t)i * DMODEL + w * 64 + d0]     = acc0 * invl;
    attn_out[(size_t)i * DMODEL + w * 64 + d0 + 1] = acc1 * invl;
}

// ---------------------------------------------------------------------------
extern "C" void kernel_launch(void* const* d_in, const int* in_sizes, int n_in,
                              void* d_out, int out_size)
{
    const float* x   = (const float*)d_in[0];
    const float* S   = (const float*)d_in[1];
    const float* Wq  = (const float*)d_in[2];
    const float* bq  = (const float*)d_in[3];
    const float* Wk  = (const float*)d_in[4];
    const float* bk  = (const float*)d_in[5];
    const float* Wv  = (const float*)d_in[6];
    const float* bv  = (const float*)d_in[7];
    const float* Wo  = (const float*)d_in[8];
    const float* bo  = (const float*)d_in[9];
    const float* Wsk = (const float*)d_in[10];
    const float* bsk = (const float*)d_in[11];
    const float* Wsv = (const float*)d_in[12];
    const float* bsv = (const float*)d_in[13];
    float* out = (float*)d_out;

    float *qp, *kp, *vp, *ap;
    cudaGetSymbolAddress((void**)&qp, g_q);
    cudaGetSymbolAddress((void**)&kp, g_k);
    cudaGetSymbolAddress((void**)&vp, g_v);
    cudaGetSymbolAddress((void**)&ap, g_attn);

    dim3 gg(DMODEL / 64, NSEQ / 64);
    gemm_bias<<<gg, 256>>>(x, Wq, bq, qp, NSEQ, DMODEL, DMODEL, 1);
    gemm_bias<<<gg, 256>>>(x, Wk, bk, kp, NSEQ, DMODEL, DMODEL, 1);
    gemm_bias<<<gg, 256>>>(x, Wv, bv, vp, NSEQ, DMODEL, DMODEL, 0);

    attn_fused<<<NSEQ, 256>>>(S, Wsk, bsk, Wsv, bsv, ap);

    gemm_bias<<<gg, 256>>>(ap, Wo, bo, out, NSEQ, DMODEL, DMODEL, 0);
}

// round 5
// speedup vs baseline: 8.4834x; 8.4834x over previous
#include <cuda_runtime.h>
#include <math.h>

#define NSEQ 1024
#define DM 512
#define NH 8
#define DK 64
#define BI 4
#define JT 32

// scratch (no cudaMalloc allowed)
__device__ float g_q[NSEQ * DM];
__device__ float g_k[NSEQ * DM];
__device__ float g_v[NSEQ * DM];
__device__ float g_attn[NSEQ * DM];
__device__ float g_qk[(size_t)NH * NSEQ * NSEQ];   // 32MB: precomputed q.k per head

__device__ __forceinline__ unsigned f2tf(float f) {
    unsigned u; asm("cvt.rna.tf32.f32 %0, %1;" : "=r"(u) : "f"(f)); return u;
}
__device__ __forceinline__ void mma8(float* c, unsigned a0, unsigned a1, unsigned a2,
                                     unsigned a3, unsigned b0, unsigned b1) {
    asm("mma.sync.aligned.m16n8k8.row.col.f32.tf32.tf32.f32 "
        "{%0,%1,%2,%3},{%4,%5,%6,%7},{%8,%9},{%0,%1,%2,%3};"
        : "+f"(c[0]), "+f"(c[1]), "+f"(c[2]), "+f"(c[3])
        : "r"(a0), "r"(a1), "r"(a2), "r"(a3), "r"(b0), "r"(b1));
}

// ---------------------------------------------------------------------------
// Projection GEMM: C = A[M,K] @ B[K,N] + bias (optional relu). fp32 SIMT.
// ---------------------------------------------------------------------------
__global__ void __launch_bounds__(256) gemm_bias(
    const float* __restrict__ A, const float* __restrict__ B,
    const float* __restrict__ bias, float* __restrict__ C,
    int M, int K, int N, int relu)
{
    __shared__ float As[16][65];
    __shared__ float Bs[16][64];
    const int bm = blockIdx.y * 64;
    const int bn = blockIdx.x * 64;
    const int tid = threadIdx.x;
    const int tx = tid & 15;
    const int ty = tid >> 4;
    float acc[4][4] = {};

    for (int k0 = 0; k0 < K; k0 += 16) {
        {
            int q = tid * 4;
            int r = q >> 4, c = q & 15;
            float4 av = *(const float4*)(A + (size_t)(bm + r) * K + k0 + c);
            As[c + 0][r] = av.x; As[c + 1][r] = av.y;
            As[c + 2][r] = av.z; As[c + 3][r] = av.w;
        }
        {
            int q = tid * 4;
            int r = q >> 6, c = q & 63;
            *(float4*)&Bs[r][c] = *(const float4*)(B + (size_t)(k0 + r) * N + bn + c);
        }
        __syncthreads();
        #pragma unroll
        for (int kk = 0; kk < 16; kk++) {
            float a[4], b[4];
            #pragma unroll
            for (int u = 0; u < 4; u++) a[u] = As[kk][ty * 4 + u];
            #pragma unroll
            for (int u = 0; u < 4; u++) b[u] = Bs[kk][tx * 4 + u];
            #pragma unroll
            for (int r = 0; r < 4; r++)
                #pragma unroll
                for (int c = 0; c < 4; c++)
                    acc[r][c] += a[r] * b[c];
        }
        __syncthreads();
    }
    #pragma unroll
    for (int r = 0; r < 4; r++) {
        int row = bm + ty * 4 + r;
        #pragma unroll
        for (int c = 0; c < 4; c++) {
            int col = bn + tx * 4 + c;
            float v = acc[r][c] + bias[col];
            if (relu) v = fmaxf(v, 0.0f);
            C[(size_t)row * N + col] = v;
        }
    }
}

// ---------------------------------------------------------------------------
// QK precompute: g_qk[h,i,j] = sum_d q[i,h,d]*k[j,h,d]  via tf32 mma.
// grid (8 jt, 8 it, 8 h), 256 thr, tile 128x128, K=64.
// ---------------------------------------------------------------------------
#define QK_SMEM (2 * 128 * 68 * 4)
__global__ void __launch_bounds__(256) qk_mma()
{
    extern __shared__ unsigned sm[];
    unsigned* sQ = sm;
    unsigned* sK = sm + 128 * 68;
    const int t = threadIdx.x, lane = t & 31, w = t >> 5;
    const int g = lane >> 2, tig = lane & 3;
    const int h = blockIdx.z, i0 = blockIdx.y * 128, j0 = blockIdx.x * 128;

    #pragma unroll
    for (int u = 0; u < 8; u++) {
        int f4 = t + 256 * u;
        int row = f4 >> 4;
        int c4 = (f4 & 15) * 4;
        float4 qv = *(const float4*)&g_q[(size_t)(i0 + row) * DM + h * DK + c4];
        unsigned* dq = sQ + row * 68 + c4;
        dq[0] = f2tf(qv.x); dq[1] = f2tf(qv.y); dq[2] = f2tf(qv.z); dq[3] = f2tf(qv.w);
        float4 kv = *(const float4*)&g_k[(size_t)(j0 + row) * DM + h * DK + c4];
        unsigned* dk = sK + row * 68 + c4;
        dk[0] = f2tf(kv.x); dk[1] = f2tf(kv.y); dk[2] = f2tf(kv.z); dk[3] = f2tf(kv.w);
    }
    __syncthreads();

    float c[16][4] = {};
    #pragma unroll
    for (int k0 = 0; k0 < 64; k0 += 8) {
        unsigned a0 = sQ[(16 * w + g) * 68 + k0 + tig];
        unsigned a1 = sQ[(16 * w + g + 8) * 68 + k0 + tig];
        unsigned a2 = sQ[(16 * w + g) * 68 + k0 + tig + 4];
        unsigned a3 = sQ[(16 * w + g + 8) * 68 + k0 + tig + 4];
        #pragma unroll
        for (int nt = 0; nt < 16; nt++) {
            unsigned b0 = sK[(8 * nt + g) * 68 + k0 + tig];
            unsigned b1 = sK[(8 * nt + g) * 68 + k0 + tig + 4];
            mma8(c[nt], a0, a1, a2, a3, b0, b1);
        }
    }
    size_t base = ((size_t)h << 20);
    #pragma unroll
    for (int nt = 0; nt < 16; nt++) {
        int jj = j0 + 8 * nt + 2 * tig;
        int ii = i0 + 16 * w + g;
        *(float2*)&g_qk[base + (size_t)ii * NSEQ + jj] = make_float2(c[nt][0], c[nt][1]);
        *(float2*)&g_qk[base + (size_t)(ii + 8) * NSEQ + jj] = make_float2(c[nt][2], c[nt][3]);
    }
}

// ---------------------------------------------------------------------------
// Fused structure attention. CTA handles BI=4 query rows, 256 thr (8 warps).
// Per 32-wide j tile and per bi: edge GEMM (tf32 mma) -> SK (transposed) /
// SV in SMEM, scores (QK precomputed + q.SK), online softmax; then one
// v-pass shared across all bi.
// ---------------------------------------------------------------------------
#define OW   0            // sW  : 64*136 tf32
#define OE   8704         // sE  : 32*68 tf32
#define OSKT 10880        // sSKT: [64 dd][68 pitch] float
#define OSV  15232        // sSV : [BI][32*68] float
#define OQ   23936        // sq  : [BI][512] float
#define OP   25984        // sP  : [BI][8][32] float
#define OBK  27008        // bsk[64]
#define OBV  27072        // bsv[64]
#define ATTN_WORDS 27136
#define ATTN_SMEM (ATTN_WORDS * 4)

__global__ void __launch_bounds__(256) attn2(
    const float* __restrict__ S,
    const float* __restrict__ Wsk, const float* __restrict__ bsk,
    const float* __restrict__ Wsv, const float* __restrict__ bsv,
    float* __restrict__ out)
{
    extern __shared__ unsigned sm[];
    unsigned* sW = sm + OW;
    unsigned* sE = sm + OE;
    float* smf  = (float*)sm;
    float* sSKT = smf + OSKT;
    float* sSV  = smf + OSV;
    float* sq   = smf + OQ;
    float* sP   = smf + OP;
    float* sBk  = smf + OBK;
    float* sBv  = smf + OBV;

    const int t = threadIdx.x, lane = t & 31, w = t >> 5;
    const int g = lane >> 2, tig = lane & 3;
    const int i0 = blockIdx.x * BI;

    // stage weights (tf32), q rows, biases
    #pragma unroll
    for (int u = 0; u < 8; u++) {
        int f4 = t + 256 * u;
        int e = f4 >> 5;
        int c4 = (f4 & 31) * 4;
        const float* src = (c4 < 64) ? (Wsk + e * 64 + c4) : (Wsv + e * 64 + c4 - 64);
        float4 v = *(const float4*)src;
        unsigned* dst = sW + e * 136 + c4;
        dst[0] = f2tf(v.x); dst[1] = f2tf(v.y); dst[2] = f2tf(v.z); dst[3] = f2tf(v.w);
    }
    #pragma unroll
    for (int u = 0; u < 2; u++) {
        int f4 = t + 256 * u;
        int bi = f4 >> 7;
        int c4 = (f4 & 127) * 4;
        *(float4*)&sq[bi * 512 + c4] = *(const float4*)&g_q[(size_t)(i0 + bi) * DM + c4];
    }
    if (t < 64) { sBk[t] = bsk[t]; sBv[t] = bsv[t]; }

    float m[BI], l[BI], fac[BI], ax[BI], ay[BI];
    #pragma unroll
    for (int b = 0; b < BI; b++) { m[b] = -1e30f; l[b] = 0.f; ax[b] = 0.f; ay[b] = 0.f; }

    const int mrow = w & 1, nq = w >> 1;
    const int dd0 = nq * 32;
    const int jr = 16 * mrow + g;

    for (int j0 = 0; j0 < NSEQ; j0 += JT) {
        #pragma unroll 1
        for (int bi = 0; bi < BI; bi++) {
            __syncthreads();
            // load structure tile -> sE (tf32)
            #pragma unroll
            for (int u = 0; u < 2; u++) {
                int f4 = t + 256 * u;
                int j = f4 >> 4;
                int e4 = (f4 & 15) * 4;
                float4 ev = *(const float4*)&S[((size_t)(i0 + bi) * NSEQ + j0 + j) * 64 + e4];
                unsigned* dst = sE + j * 68 + e4;
                dst[0] = f2tf(ev.x); dst[1] = f2tf(ev.y);
                dst[2] = f2tf(ev.z); dst[3] = f2tf(ev.w);
            }
            __syncthreads();
            // edge GEMM: [32 j x 64 e] @ [64 e x 128 dd]
            float c[4][4] = {};
            #pragma unroll
            for (int k = 0; k < 8; k++) {
                int k0 = k * 8;
                unsigned a0 = sE[jr * 68 + k0 + tig];
                unsigned a1 = sE[(jr + 8) * 68 + k0 + tig];
                unsigned a2 = sE[jr * 68 + k0 + tig + 4];
                unsigned a3 = sE[(jr + 8) * 68 + k0 + tig + 4];
                #pragma unroll
                for (int nt = 0; nt < 4; nt++) {
                    int dd = dd0 + 8 * nt;
                    unsigned b0 = sW[(k0 + tig) * 136 + dd + g];
                    unsigned b1 = sW[(k0 + tig + 4) * 136 + dd + g];
                    mma8(c[nt], a0, a1, a2, a3, b0, b1);
                }
            }
            // store: warps 0-1 -> SK (relu, transposed [dd][j]); warps 2-3 -> SV
            if (nq < 2) {
                #pragma unroll
                for (int nt = 0; nt < 4; nt++) {
                    int dd = dd0 + 8 * nt + 2 * tig;
                    float b0v = sBk[dd], b1v = sBk[dd + 1];
                    sSKT[dd * 68 + jr]           = fmaxf(c[nt][0] + b0v, 0.f);
                    sSKT[(dd + 1) * 68 + jr]     = fmaxf(c[nt][1] + b1v, 0.f);
                    sSKT[dd * 68 + jr + 8]       = fmaxf(c[nt][2] + b0v, 0.f);
                    sSKT[(dd + 1) * 68 + jr + 8] = fmaxf(c[nt][3] + b1v, 0.f);
                }
            } else {
                float* SVb = sSV + bi * 2176;
                #pragma unroll
                for (int nt = 0; nt < 4; nt++) {
                    int dv = dd0 - 64 + 8 * nt + 2 * tig;
                    float b0v = sBv[dv], b1v = sBv[dv + 1];
                    *(float2*)&SVb[jr * 68 + dv]       = make_float2(c[nt][0] + b0v, c[nt][1] + b1v);
                    *(float2*)&SVb[(jr + 8) * 68 + dv] = make_float2(c[nt][2] + b0v, c[nt][3] + b1v);
                }
            }
            __syncthreads();
            // scores: warp w = head, lane = j
            const float* qh = sq + bi * 512 + w * 64;
            float s2 = 0.f;
            #pragma unroll
            for (int d4 = 0; d4 < 64; d4 += 4) {
                float4 qv = *(const float4*)&qh[d4];
                s2 += qv.x * sSKT[(d4 + 0) * 68 + lane]
                    + qv.y * sSKT[(d4 + 1) * 68 + lane]
                    + qv.z * sSKT[(d4 + 2) * 68 + lane]
                    + qv.w * sSKT[(d4 + 3) * 68 + lane];
            }
            float s = (g_qk[((size_t)w << 20) + (size_t)(i0 + bi) * NSEQ + j0 + lane] + s2) * 0.125f;
            float mx = s;
            #pragma unroll
            for (int o = 16; o > 0; o >>= 1)
                mx = fmaxf(mx, __shfl_xor_sync(0xffffffffu, mx, o));
            float mn = fmaxf(m[bi], mx);
            fac[bi] = __expf(m[bi] - mn);
            float p = __expf(s - mn);
            float ps = p;
            #pragma unroll
            for (int o = 16; o > 0; o >>= 1)
                ps += __shfl_xor_sync(0xffffffffu, ps, o);
            l[bi] = l[bi] * fac[bi] + ps;
            m[bi] = mn;
            sP[(bi * 8 + w) * 32 + lane] = p;
        }
        __syncthreads();
        // aggregation: one v pass, reused across all bi
        #pragma unroll
        for (int b = 0; b < BI; b++) { ax[b] *= fac[b]; ay[b] *= fac[b]; }
        const float* vbase = g_v + (size_t)j0 * DM + w * 64 + 2 * lane;
        #pragma unroll 4
        for (int j = 0; j < JT; j++) {
            float2 vv = *(const float2*)(vbase + (size_t)j * DM);
            #pragma unroll
            for (int b = 0; b < BI; b++) {
                float p = sP[(b * 8 + w) * 32 + j];
                float2 sv = *(const float2*)&sSV[b * 2176 + j * 68 + 2 * lane];
                ax[b] += p * (vv.x + sv.x);
                ay[b] += p * (vv.y + sv.y);
            }
        }
    }
    #pragma unroll
    for (int b = 0; b < BI; b++) {
        float inv = 1.f / l[b];
        *(float2*)&out[(size_t)(i0 + b) * DM + w * 64 + 2 * lane] =
            make_float2(ax[b] * inv, ay[b] * inv);
    }
}

// ---------------------------------------------------------------------------
extern "C" void kernel_launch(void* const* d_in, const int* in_sizes, int n_in,
                              void* d_out, int out_size)
{
    const float* x   = (const float*)d_in[0];
    const float* S   = (const float*)d_in[1];
    const float* Wq  = (const float*)d_in[2];
    const float* bq  = (const float*)d_in[3];
    const float* Wk  = (const float*)d_in[4];
    const float* bk  = (const float*)d_in[5];
    const float* Wv  = (const float*)d_in[6];
    const float* bv  = (const float*)d_in[7];
    const float* Wo  = (const float*)d_in[8];
    const float* bo  = (const float*)d_in[9];
    const float* Wsk = (const float*)d_in[10];
    const float* bsk = (const float*)d_in[11];
    const float* Wsv = (const float*)d_in[12];
    const float* bsv = (const float*)d_in[13];
    float* out = (float*)d_out;

    float *qp, *kp, *vp, *ap;
    cudaGetSymbolAddress((void**)&qp, g_q);
    cudaGetSymbolAddress((void**)&kp, g_k);
    cudaGetSymbolAddress((void**)&vp, g_v);
    cudaGetSymbolAddress((void**)&ap, g_attn);

    cudaFuncSetAttribute(qk_mma, cudaFuncAttributeMaxDynamicSharedMemorySize, QK_SMEM);
    cudaFuncSetAttribute(attn2, cudaFuncAttributeMaxDynamicSharedMemorySize, ATTN_SMEM);

    dim3 gg(DM / 64, NSEQ / 64);
    gemm_bias<<<gg, 256>>>(x, Wq, bq, qp, NSEQ, DM, DM, 1);
    gemm_bias<<<gg, 256>>>(x, Wk, bk, kp, NSEQ, DM, DM, 1);
    gemm_bias<<<gg, 256>>>(x, Wv, bv, vp, NSEQ, DM, DM, 0);

    qk_mma<<<dim3(8, 8, 8), 256, QK_SMEM>>>();

    attn2<<<NSEQ / BI, 256, ATTN_SMEM>>>(S, Wsk, bsk, Wsv, bsv, ap);

    gemm_bias<<<gg, 256>>>(ap, Wo, bo, out, NSEQ, DM, DM, 0);
}

// round 7
// speedup vs baseline: 11.0403x; 1.3014x over previous
#include <cuda_runtime.h>
#include <cuda_bf16.h>
#include <math.h>

#define NSEQ 1024
#define DM 512
#define NH 8
#define DK 64

// scratch (no cudaMalloc allowed)
__device__ float g_q[NSEQ * DM];
__device__ float g_k[NSEQ * DM];
__device__ float g_v[NSEQ * DM];
__device__ float g_attn[NSEQ * DM];
__device__ float g_pv[NSEQ * DM];
__device__ float g_qk[(size_t)NH * NSEQ * NSEQ];          // 32MB: scores -> probs (in place)
__device__ __nv_bfloat16 g_sv[(size_t)NSEQ * NSEQ * DK];  // 128MB: structure-value proj

__device__ __forceinline__ unsigned f2tf(float f) {
    unsigned u; asm("cvt.rna.tf32.f32 %0, %1;" : "=r"(u) : "f"(f)); return u;
}
__device__ __forceinline__ void mma8(float* c, unsigned a0, unsigned a1, unsigned a2,
                                     unsigned a3, unsigned b0, unsigned b1) {
    asm("mma.sync.aligned.m16n8k8.row.col.f32.tf32.tf32.f32 "
        "{%0,%1,%2,%3},{%4,%5,%6,%7},{%8,%9},{%0,%1,%2,%3};"
        : "+f"(c[0]), "+f"(c[1]), "+f"(c[2]), "+f"(c[3])
        : "r"(a0), "r"(a1), "r"(a2), "r"(a3), "r"(b0), "r"(b1));
}

// ---------------------------------------------------------------------------
// Projection GEMM: C = A[M,K] @ B[K,N] + bias (optional relu). fp32 SIMT.
// ---------------------------------------------------------------------------
__global__ void __launch_bounds__(256) gemm_bias(
    const float* __restrict__ A, const float* __restrict__ B,
    const float* __restrict__ bias, float* __restrict__ C,
    int M, int K, int N, int relu)
{
    __shared__ float As[16][65];
    __shared__ float Bs[16][64];
    const int bm = blockIdx.y * 64;
    const int bn = blockIdx.x * 64;
    const int tid = threadIdx.x;
    const int tx = tid & 15;
    const int ty = tid >> 4;
    float acc[4][4] = {};

    for (int k0 = 0; k0 < K; k0 += 16) {
        {
            int q = tid * 4;
            int r = q >> 4, c = q & 15;
            float4 av = *(const float4*)(A + (size_t)(bm + r) * K + k0 + c);
            As[c + 0][r] = av.x; As[c + 1][r] = av.y;
            As[c + 2][r] = av.z; As[c + 3][r] = av.w;
        }
        {
            int q = tid * 4;
            int r = q >> 6, c = q & 63;
            *(float4*)&Bs[r][c] = *(const float4*)(B + (size_t)(k0 + r) * N + bn + c);
        }
        __syncthreads();
        #pragma unroll
        for (int kk = 0; kk < 16; kk++) {
            float a[4], b[4];
            #pragma unroll
            for (int u = 0; u < 4; u++) a[u] = As[kk][ty * 4 + u];
            #pragma unroll
            for (int u = 0; u < 4; u++) b[u] = Bs[kk][tx * 4 + u];
            #pragma unroll
            for (int r = 0; r < 4; r++)
                #pragma unroll
                for (int c = 0; c < 4; c++)
                    acc[r][c] += a[r] * b[c];
        }
        __syncthreads();
    }
    #pragma unroll
    for (int r = 0; r < 4; r++) {
        int row = bm + ty * 4 + r;
        #pragma unroll
        for (int c = 0; c < 4; c++) {
            int col = bn + tx * 4 + c;
            float v = acc[r][c] + bias[col];
            if (relu) v = fmaxf(v, 0.0f);
            C[(size_t)row * N + col] = v;
        }
    }
}

// ---------------------------------------------------------------------------
// QK precompute: g_qk[h,i,j] = sum_d q[i,h,d]*k[j,h,d]  (raw, unscaled)
// ---------------------------------------------------------------------------
#define QK_SMEM (2 * 128 * 68 * 4)
__global__ void __launch_bounds__(256) qk_mma()
{
    extern __shared__ unsigned sm[];
    unsigned* sQ = sm;
    unsigned* sK = sm + 128 * 68;
    const int t = threadIdx.x, lane = t & 31, w = t >> 5;
    const int g = lane >> 2, tig = lane & 3;
    const int h = blockIdx.z, i0 = blockIdx.y * 128, j0 = blockIdx.x * 128;

    #pragma unroll
    for (int u = 0; u < 8; u++) {
        int f4 = t + 256 * u;
        int row = f4 >> 4;
        int c4 = (f4 & 15) * 4;
        float4 qv = *(const float4*)&g_q[(size_t)(i0 + row) * DM + h * DK + c4];
        unsigned* dq = sQ + row * 68 + c4;
        dq[0] = f2tf(qv.x); dq[1] = f2tf(qv.y); dq[2] = f2tf(qv.z); dq[3] = f2tf(qv.w);
        float4 kv = *(const float4*)&g_k[(size_t)(j0 + row) * DM + h * DK + c4];
        unsigned* dk = sK + row * 68 + c4;
        dk[0] = f2tf(kv.x); dk[1] = f2tf(kv.y); dk[2] = f2tf(kv.z); dk[3] = f2tf(kv.w);
    }
    __syncthreads();

    float c[16][4] = {};
    #pragma unroll
    for (int k0 = 0; k0 < 64; k0 += 8) {
        unsigned a0 = sQ[(16 * w + g) * 68 + k0 + tig];
        unsigned a1 = sQ[(16 * w + g + 8) * 68 + k0 + tig];
        unsigned a2 = sQ[(16 * w + g) * 68 + k0 + tig + 4];
        unsigned a3 = sQ[(16 * w + g + 8) * 68 + k0 + tig + 4];
        #pragma unroll
        for (int nt = 0; nt < 16; nt++) {
            unsigned b0 = sK[(8 * nt + g) * 68 + k0 + tig];
            unsigned b1 = sK[(8 * nt + g) * 68 + k0 + tig + 4];
            mma8(c[nt], a0, a1, a2, a3, b0, b1);
        }
    }
    size_t base = ((size_t)h << 20);
    #pragma unroll
    for (int nt = 0; nt < 16; nt++) {
        int jj = j0 + 8 * nt + 2 * tig;
        int ii = i0 + 16 * w + g;
        *(float2*)&g_qk[base + (size_t)ii * NSEQ + jj] = make_float2(c[nt][0], c[nt][1]);
        *(float2*)&g_qk[base + (size_t)(ii + 8) * NSEQ + jj] = make_float2(c[nt][2], c[nt][3]);
    }
}

// ---------------------------------------------------------------------------
// edge_fused: per (i, 128-wide j tile):
//   [128j x 64e] @ [64e x 128dd] tf32 MMA -> sk (smem, relu) | sv (-> g_sv bf16)
//   score MMA: sk[128x64] @ qT[64x8] -> g_qk[h,i,j] = (qk + q.sk)*0.125  (in place)
// smem words: sW 8704 | sE 8704 (->SV stage) | sSK 8704 | sQT 576 | sB 128
// ---------------------------------------------------------------------------
#define P2_SMEM ((8704 * 3 + 576 + 128) * 4)
__global__ void __launch_bounds__(256, 2) edge_fused(
    const float* __restrict__ S,
    const float* __restrict__ Wsk, const float* __restrict__ bsk,
    const float* __restrict__ Wsv, const float* __restrict__ bsv)
{
    extern __shared__ unsigned sm2[];
    unsigned* sW  = sm2;                 // [64][136]
    unsigned* sE  = sm2 + 8704;          // [128][68] tf32 E; later fp32 SV stage
    unsigned* sSK = sm2 + 17408;         // [128][68] tf32 sk
    unsigned* sQT = sm2 + 26112;         // [64][9]
    float*    sB  = (float*)(sm2 + 26688); // bsk[0:64) | bsv[64:128)
    float*    sSV = (float*)sE;

    const int t = threadIdx.x, lane = t & 31, w = t >> 5;
    const int g = lane >> 2, tig = lane & 3;
    const int i  = blockIdx.y;
    const int j0 = blockIdx.x * 128;

    // stage W (Wsk|Wsv) as tf32, pitch 136
    #pragma unroll
    for (int u = 0; u < 8; u++) {
        int f4 = t + 256 * u;
        int e = f4 >> 5;
        int c4 = (f4 & 31) * 4;
        const float* src = (c4 < 64) ? (Wsk + e * 64 + c4) : (Wsv + e * 64 + c4 - 64);
        float4 v = *(const float4*)src;
        unsigned* dst = sW + e * 136 + c4;
        dst[0] = f2tf(v.x); dst[1] = f2tf(v.y); dst[2] = f2tf(v.z); dst[3] = f2tf(v.w);
    }
    // stage E tile [128 x 64] tf32
    #pragma unroll
    for (int u = 0; u < 8; u++) {
        int f4 = t + 256 * u;
        int j = f4 >> 4;
        int e4 = (f4 & 15) * 4;
        float4 v = *(const float4*)&S[((size_t)i * NSEQ + j0 + j) * 64 + e4];
        unsigned* dst = sE + j * 68 + e4;
        dst[0] = f2tf(v.x); dst[1] = f2tf(v.y); dst[2] = f2tf(v.z); dst[3] = f2tf(v.w);
    }
    // stage qT [d][h]
    #pragma unroll
    for (int u = 0; u < 2; u++) {
        int idx = t + 256 * u;
        sQT[(idx & 63) * 9 + (idx >> 6)] = f2tf(g_q[(size_t)i * DM + idx]);
    }
    if (t < 128) sB[t] = (t < 64) ? bsk[t] : bsv[t - 64];
    __syncthreads();

    // GEMM1: warp = (mq = w&3 -> 32 rows, ng = w>>2 -> 64 cols)
    const int mq = w & 3, ng = w >> 2;
    float c[2][8][4] = {};
    #pragma unroll
    for (int k = 0; k < 8; k++) {
        int k0 = k * 8;
        unsigned a[2][4];
        #pragma unroll
        for (int mt = 0; mt < 2; mt++) {
            int r0 = mq * 32 + mt * 16;
            a[mt][0] = sE[(r0 + g) * 68 + k0 + tig];
            a[mt][1] = sE[(r0 + g + 8) * 68 + k0 + tig];
            a[mt][2] = sE[(r0 + g) * 68 + k0 + tig + 4];
            a[mt][3] = sE[(r0 + g + 8) * 68 + k0 + tig + 4];
        }
        #pragma unroll
        for (int nt = 0; nt < 8; nt++) {
            int dd = ng * 64 + nt * 8;
            unsigned b0 = sW[(k0 + tig) * 136 + dd + g];
            unsigned b1 = sW[(k0 + tig + 4) * 136 + dd + g];
            mma8(c[0][nt], a[0][0], a[0][1], a[0][2], a[0][3], b0, b1);
            mma8(c[1][nt], a[1][0], a[1][1], a[1][2], a[1][3], b0, b1);
        }
    }

    // ng==0 warps: sk = relu(c + bsk) -> sSK (tf32)  [before barrier]
    if (ng == 0) {
        #pragma unroll
        for (int mt = 0; mt < 2; mt++) {
            int r0 = mq * 32 + mt * 16;
            #pragma unroll
            for (int nt = 0; nt < 8; nt++) {
                int dd = nt * 8 + 2 * tig;
                float b0v = sB[dd], b1v = sB[dd + 1];
                sSK[(r0 + g) * 68 + dd]         = f2tf(fmaxf(c[mt][nt][0] + b0v, 0.f));
                sSK[(r0 + g) * 68 + dd + 1]     = f2tf(fmaxf(c[mt][nt][1] + b1v, 0.f));
                sSK[(r0 + g + 8) * 68 + dd]     = f2tf(fmaxf(c[mt][nt][2] + b0v, 0.f));
                sSK[(r0 + g + 8) * 68 + dd + 1] = f2tf(fmaxf(c[mt][nt][3] + b1v, 0.f));
            }
        }
    }
    __syncthreads();   // sSK complete; sE free for SV staging
    if (ng == 1) {
        #pragma unroll
        for (int mt = 0; mt < 2; mt++) {
            int r0 = mq * 32 + mt * 16;
            #pragma unroll
            for (int nt = 0; nt < 8; nt++) {
                int dv = nt * 8 + 2 * tig;
                float b0v = sB[64 + dv], b1v = sB[64 + dv + 1];
                sSV[(r0 + g) * 68 + dv]         = c[mt][nt][0] + b0v;
                sSV[(r0 + g) * 68 + dv + 1]     = c[mt][nt][1] + b1v;
                sSV[(r0 + g + 8) * 68 + dv]     = c[mt][nt][2] + b0v;
                sSV[(r0 + g + 8) * 68 + dv + 1] = c[mt][nt][3] + b1v;
            }
        }
    }

    // score MMA: s2[128j x 8h] = sk @ qT ; warp w = m16 tile (rows 16w)
    float cs[4] = {};
    #pragma unroll
    for (int k = 0; k < 8; k++) {
        int k0 = k * 8;
        unsigned a0 = sSK[(16 * w + g) * 68 + k0 + tig];
        unsigned a1 = sSK[(16 * w + g + 8) * 68 + k0 + tig];
        unsigned a2 = sSK[(16 * w + g) * 68 + k0 + tig + 4];
        unsigned a3 = sSK[(16 * w + g + 8) * 68 + k0 + tig + 4];
        unsigned b0 = sQT[(k0 + tig) * 9 + g];
        unsigned b1 = sQT[(k0 + tig + 4) * 9 + g];
        mma8(cs, a0, a1, a2, a3, b0, b1);
    }
    // epilogue: g_qk[h,i,j] = (qk + s2) * 0.125
    {
        int h0 = 2 * tig;
        int jr = 16 * w + g;
        size_t ibase = ((size_t)i << 10) + j0;
        size_t p00 = ((size_t)h0 << 20) + ibase + jr;
        size_t p01 = ((size_t)(h0 + 1) << 20) + ibase + jr;
        g_qk[p00]     = (g_qk[p00]     + cs[0]) * 0.125f;
        g_qk[p01]     = (g_qk[p01]     + cs[1]) * 0.125f;
        g_qk[p00 + 8] = (g_qk[p00 + 8] + cs[2]) * 0.125f;
        g_qk[p01 + 8] = (g_qk[p01 + 8] + cs[3]) * 0.125f;
    }
    __syncthreads();   // sSV complete

    // cooperative SV write: fp32 smem -> bf16 gmem, coalesced
    #pragma unroll
    for (int u = 0; u < 4; u++) {
        int idx = t + 256 * u;          // 1024 groups of 8 floats
        int j = idx >> 3;
        int d0 = (idx & 7) * 8;
        const float* src = &sSV[j * 68 + d0];
        __nv_bfloat162 b0 = __float22bfloat162_rn(make_float2(src[0], src[1]));
        __nv_bfloat162 b1 = __float22bfloat162_rn(make_float2(src[2], src[3]));
        __nv_bfloat162 b2 = __float22bfloat162_rn(make_float2(src[4], src[5]));
        __nv_bfloat162 b3 = __float22bfloat162_rn(make_float2(src[6], src[7]));
        uint4 pkt;
        pkt.x = *(unsigned*)&b0; pkt.y = *(unsigned*)&b1;
        pkt.z = *(unsigned*)&b2; pkt.w = *(unsigned*)&b3;
        *(uint4*)((char*)g_sv + (((size_t)i << 10) + j0 + j) * 128 + d0 * 2) = pkt;
    }
}

// ---------------------------------------------------------------------------
// softmax over rows of g_qk (8192 rows of 1024), normalized, in place.
// ---------------------------------------------------------------------------
__global__ void __launch_bounds__(256) softmax_rows()
{
    __shared__ float rbuf[8];
    const int t = threadIdx.x, lane = t & 31, w = t >> 5;
    float4* row4 = (float4*)(g_qk + ((size_t)blockIdx.x << 10));
    float4 v = row4[t];

    float mx = fmaxf(fmaxf(v.x, v.y), fmaxf(v.z, v.w));
    #pragma unroll
    for (int o = 16; o > 0; o >>= 1) mx = fmaxf(mx, __shfl_xor_sync(0xffffffffu, mx, o));
    if (lane == 0) rbuf[w] = mx;
    __syncthreads();
    if (t < 32) {
        float z = (lane < 8) ? rbuf[lane] : -1e30f;
        #pragma unroll
        for (int o = 4; o > 0; o >>= 1) z = fmaxf(z, __shfl_xor_sync(0xffffffffu, z, o));
        if (lane == 0) rbuf[0] = z;
    }
    __syncthreads();
    float m = rbuf[0];
    __syncthreads();

    float4 e;
    e.x = __expf(v.x - m); e.y = __expf(v.y - m);
    e.z = __expf(v.z - m); e.w = __expf(v.w - m);
    float s = e.x + e.y + e.z + e.w;
    #pragma unroll
    for (int o = 16; o > 0; o >>= 1) s += __shfl_xor_sync(0xffffffffu, s, o);
    if (lane == 0) rbuf[w] = s;
    __syncthreads();
    if (t < 32) {
        float z = (lane < 8) ? rbuf[lane] : 0.f;
        #pragma unroll
        for (int o = 4; o > 0; o >>= 1) z += __shfl_xor_sync(0xffffffffu, z, o);
        if (lane == 0) rbuf[0] = z;
    }
    __syncthreads();
    float inv = 1.0f / rbuf[0];
    e.x *= inv; e.y *= inv; e.z *= inv; e.w *= inv;
    row4[t] = e;
}

// ---------------------------------------------------------------------------
// pv_gemm: PV[i, h*64+d] = sum_j p[h,i,j] * v[j, h*64+d]. grid (16 it, 8 h).
// ---------------------------------------------------------------------------
__global__ void __launch_bounds__(256) pv_gemm()
{
    __shared__ unsigned sP[64 * 68];
    __shared__ unsigned sV[64 * 68];
    const int t = threadIdx.x, lane = t & 31, w = t >> 5;
    const int g = lane >> 2, tig = lane & 3;
    const int i0 = blockIdx.x * 64, h = blockIdx.y;
    const int m = w & 3, nh = w >> 2;

    float c[4][4] = {};
    for (int j0 = 0; j0 < NSEQ; j0 += 64) {
        __syncthreads();
        #pragma unroll
        for (int u = 0; u < 4; u++) {
            int f4 = t + 256 * u;
            int r = f4 >> 4;
            int c4 = (f4 & 15) * 4;
            float4 pv = *(const float4*)&g_qk[((size_t)h << 20) + ((size_t)(i0 + r) << 10) + j0 + c4];
            unsigned* dp = sP + r * 68 + c4;
            dp[0] = f2tf(pv.x); dp[1] = f2tf(pv.y); dp[2] = f2tf(pv.z); dp[3] = f2tf(pv.w);
            float4 vv = *(const float4*)&g_v[(size_t)(j0 + r) * DM + h * DK + c4];
            unsigned* dv = sV + r * 68 + c4;
            dv[0] = f2tf(vv.x); dv[1] = f2tf(vv.y); dv[2] = f2tf(vv.z); dv[3] = f2tf(vv.w);
        }
        __syncthreads();
        #pragma unroll
        for (int k = 0; k < 8; k++) {
            int k0 = k * 8;
            unsigned a0 = sP[(m * 16 + g) * 68 + k0 + tig];
            unsigned a1 = sP[(m * 16 + g + 8) * 68 + k0 + tig];
            unsigned a2 = sP[(m * 16 + g) * 68 + k0 + tig + 4];
            unsigned a3 = sP[(m * 16 + g + 8) * 68 + k0 + tig + 4];
            #pragma unroll
            for (int nt = 0; nt < 4; nt++) {
                int d = nh * 32 + nt * 8;
                unsigned b0 = sV[(k0 + tig) * 68 + d + g];
                unsigned b1 = sV[(k0 + tig + 4) * 68 + d + g];
                mma8(c[nt], a0, a1, a2, a3, b0, b1);
            }
        }
    }
    #pragma unroll
    for (int nt = 0; nt < 4; nt++) {
        int d = h * 64 + nh * 32 + nt * 8 + 2 * tig;
        int r = i0 + m * 16 + g;
        *(float2*)&g_pv[(size_t)r * DM + d]       = make_float2(c[nt][0], c[nt][1]);
        *(float2*)&g_pv[(size_t)(r + 8) * DM + d] = make_float2(c[nt][2], c[nt][3]);
    }
}

// ---------------------------------------------------------------------------
// sv_agg: attn[i, h*64+d] = PV[i,h*64+d] + sum_j p[h,i,j]*sv[i,j,d]. 1 CTA/i.
// ---------------------------------------------------------------------------
__global__ void __launch_bounds__(256) sv_agg()
{
    __shared__ unsigned sSVb[128 * 34];   // bf16x2 tile [128 j][32 dpair]
    __shared__ float pT[128 * 8];         // [j][h]
    __shared__ float red[8 * 512];        // per-warp partials
    const int t = threadIdx.x, lane = t & 31, w = t >> 5;
    const int i = blockIdx.x;

    float accx[8] = {}, accy[8] = {};
    const unsigned* svrow = (const unsigned*)g_sv + ((size_t)i << 10) * 32;

    for (int j0 = 0; j0 < NSEQ; j0 += 128) {
        __syncthreads();
        // stage SV tile (bf16x2 words), coalesced
        #pragma unroll
        for (int u = 0; u < 16; u++) {
            int idx = t + 256 * u;        // 4096 words
            int j = idx >> 5, dp = idx & 31;
            sSVb[j * 34 + dp] = svrow[(size_t)(j0 + j) * 32 + dp];
        }
        // stage p transposed [j][h]
        #pragma unroll
        for (int u = 0; u < 4; u++) {
            int idx = t + 256 * u;        // 1024
            int h = idx >> 7, j = idx & 127;
            pT[j * 8 + h] = g_qk[((size_t)h << 20) + ((size_t)i << 10) + j0 + j];
        }
        __syncthreads();
        for (int jj = w; jj < 128; jj += 8) {
            float4 pA = *(float4*)&pT[jj * 8];
            float4 pB = *(float4*)&pT[jj * 8 + 4];
            __nv_bfloat162 svb = *(__nv_bfloat162*)&sSVb[jj * 34 + lane];
            float2 sv = __bfloat1622float2(svb);
            accx[0] += pA.x * sv.x; accy[0] += pA.x * sv.y;
            accx[1] += pA.y * sv.x; accy[1] += pA.y * sv.y;
            accx[2] += pA.z * sv.x; accy[2] += pA.z * sv.y;
            accx[3] += pA.w * sv.x; accy[3] += pA.w * sv.y;
            accx[4] += pB.x * sv.x; accy[4] += pB.x * sv.y;
            accx[5] += pB.y * sv.x; accy[5] += pB.y * sv.y;
            accx[6] += pB.z * sv.x; accy[6] += pB.z * sv.y;
            accx[7] += pB.w * sv.x; accy[7] += pB.w * sv.y;
        }
    }
    __syncthreads();
    #pragma unroll
    for (int h = 0; h < 8; h++)
        *(float2*)&red[w * 512 + h * 64 + 2 * lane] = make_float2(accx[h], accy[h]);
    __syncthreads();
    int o = t * 2;
    float2 s = make_float2(0.f, 0.f);
    #pragma unroll
    for (int ww = 0; ww < 8; ww++) {
        float2 r = *(float2*)&red[ww * 512 + o];
        s.x += r.x; s.y += r.y;
    }
    float2 pv = *(float2*)&g_pv[(size_t)i * DM + o];
    *(float2*)&g_attn[(size_t)i * DM + o] = make_float2(s.x + pv.x, s.y + pv.y);
}

// ---------------------------------------------------------------------------
extern "C" void kernel_launch(void* const* d_in, const int* in_sizes, int n_in,
                              void* d_out, int out_size)
{
    const float* x   = (const float*)d_in[0];
    const float* S   = (const float*)d_in[1];
    const float* Wq  = (const float*)d_in[2];
    const float* bq  = (const float*)d_in[3];
    const float* Wk  = (const float*)d_in[4];
    const float* bk  = (const float*)d_in[5];
    const float* Wv  = (const float*)d_in[6];
    const float* bv  = (const float*)d_in[7];
    const float* Wo  = (const float*)d_in[8];
    const float* bo  = (const float*)d_in[9];
    const float* Wsk = (const float*)d_in[10];
    const float* bsk = (const float*)d_in[11];
    const float* Wsv = (const float*)d_in[12];
    const float* bsv = (const float*)d_in[13];
    float* out = (float*)d_out;

    float *qp, *kp, *vp, *ap;
    cudaGetSymbolAddress((void**)&qp, g_q);
    cudaGetSymbolAddress((void**)&kp, g_k);
    cudaGetSymbolAddress((void**)&vp, g_v);
    cudaGetSymbolAddress((void**)&ap, g_attn);

    cudaFuncSetAttribute(qk_mma, cudaFuncAttributeMaxDynamicSharedMemorySize, QK_SMEM);
    cudaFuncSetAttribute(edge_fused, cudaFuncAttributeMaxDynamicSharedMemorySize, P2_SMEM);

    dim3 gg(DM / 64, NSEQ / 64);
    gemm_bias<<<gg, 256>>>(x, Wq, bq, qp, NSEQ, DM, DM, 1);
    gemm_bias<<<gg, 256>>>(x, Wk, bk, kp, NSEQ, DM, DM, 1);
    gemm_bias<<<gg, 256>>>(x, Wv, bv, vp, NSEQ, DM, DM, 0);

    qk_mma<<<dim3(8, 8, 8), 256, QK_SMEM>>>();

    edge_fused<<<dim3(8, NSEQ), 256, P2_SMEM>>>(S, Wsk, bsk, Wsv, bsv);

    softmax_rows<<<NH * NSEQ, 256>>>();

    pv_gemm<<<dim3(16, 8), 256>>>();

    sv_agg<<<NSEQ, 256>>>();

    gemm_bias<<<gg, 256>>>(ap, Wo, bo, out, NSEQ, DM, DM, 0);
}

// round 9
// speedup vs baseline: 12.8936x; 1.1679x over previous
#include <cuda_runtime.h>
#include <cuda_bf16.h>
#include <math.h>

#define NSEQ 1024
#define DM 512
#define NH 8
#define DK 64

// scratch (no cudaMalloc allowed)
__device__ float g_q[NSEQ * DM];
__device__ float g_k[NSEQ * DM];
__device__ float g_v[NSEQ * DM];
__device__ float g_attn[NSEQ * DM];
__device__ float g_pv[NSEQ * DM];
__device__ float g_qk[(size_t)NH * NSEQ * NSEQ];          // 32MB: scores -> probs (in place)
__device__ __nv_bfloat16 g_sv[(size_t)NSEQ * NSEQ * DK];  // 128MB: structure-value proj

__device__ __forceinline__ unsigned f2tf(float f) {
    unsigned u; asm("cvt.rna.tf32.f32 %0, %1;" : "=r"(u) : "f"(f)); return u;
}
__device__ __forceinline__ void mma8(float* c, unsigned a0, unsigned a1, unsigned a2,
                                     unsigned a3, unsigned b0, unsigned b1) {
    asm("mma.sync.aligned.m16n8k8.row.col.f32.tf32.tf32.f32 "
        "{%0,%1,%2,%3},{%4,%5,%6,%7},{%8,%9},{%0,%1,%2,%3};"
        : "+f"(c[0]), "+f"(c[1]), "+f"(c[2]), "+f"(c[3])
        : "r"(a0), "r"(a1), "r"(a2), "r"(a3), "r"(b0), "r"(b1));
}

// ---------------------------------------------------------------------------
// Projection GEMM via 3xTF32 (hh + hl + lh => fp32-grade accuracy).
// C[1024,512] = A[1024,512] @ W[512,512] + bias (optional relu).
// Tile 64x64, K-chunk 32, 256 threads (warp: m16 x n32).
// ---------------------------------------------------------------------------
__global__ void __launch_bounds__(256) proj_mma(
    const float* __restrict__ A, const float* __restrict__ W,
    const float* __restrict__ bias, float* __restrict__ C, int relu)
{
    __shared__ unsigned sAhi[64 * 36], sAlo[64 * 36];
    __shared__ unsigned sWhi[32 * 68], sWlo[32 * 68];
    const int t = threadIdx.x, lane = t & 31, w = t >> 5;
    const int g = lane >> 2, tig = lane & 3;
    const int bm = blockIdx.y * 64, bn = blockIdx.x * 64;
    const int wm = w & 3, wn = w >> 2;

    float c[4][4] = {};

    for (int k0 = 0; k0 < DM; k0 += 32) {
        __syncthreads();
        #pragma unroll
        for (int u = 0; u < 2; u++) {
            int f4 = t + 256 * u;
            {   // A tile 64x32
                int r = f4 >> 3, c4 = (f4 & 7) * 4;
                float4 v = *(const float4*)&A[(size_t)(bm + r) * DM + k0 + c4];
                unsigned* dh = sAhi + r * 36 + c4;
                unsigned* dl = sAlo + r * 36 + c4;
                unsigned h0 = f2tf(v.x), h1 = f2tf(v.y), h2 = f2tf(v.z), h3 = f2tf(v.w);
                dh[0] = h0; dh[1] = h1; dh[2] = h2; dh[3] = h3;
                dl[0] = f2tf(v.x - __uint_as_float(h0));
                dl[1] = f2tf(v.y - __uint_as_float(h1));
                dl[2] = f2tf(v.z - __uint_as_float(h2));
                dl[3] = f2tf(v.w - __uint_as_float(h3));
            }
            {   // W tile 32x64
                int r = f4 >> 4, c4 = (f4 & 15) * 4;
                float4 v = *(const float4*)&W[(size_t)(k0 + r) * DM + bn + c4];
                unsigned* dh = sWhi + r * 68 + c4;
                unsigned* dl = sWlo + r * 68 + c4;
                unsigned h0 = f2tf(v.x), h1 = f2tf(v.y), h2 = f2tf(v.z), h3 = f2tf(v.w);
                dh[0] = h0; dh[1] = h1; dh[2] = h2; dh[3] = h3;
                dl[0] = f2tf(v.x - __uint_as_float(h0));
                dl[1] = f2tf(v.y - __uint_as_float(h1));
                dl[2] = f2tf(v.z - __uint_as_float(h2));
                dl[3] = f2tf(v.w - __uint_as_float(h3));
            }
        }
        __syncthreads();
        #pragma unroll
        for (int ks = 0; ks < 4; ks++) {
            int k8 = ks * 8;
            int r0 = wm * 16;
            unsigned ah0 = sAhi[(r0 + g) * 36 + k8 + tig];
            unsigned ah1 = sAhi[(r0 + g + 8) * 36 + k8 + tig];
            unsigned ah2 = sAhi[(r0 + g) * 36 + k8 + tig + 4];
            unsigned ah3 = sAhi[(r0 + g + 8) * 36 + k8 + tig + 4];
            unsigned al0 = sAlo[(r0 + g) * 36 + k8 + tig];
            unsigned al1 = sAlo[(r0 + g + 8) * 36 + k8 + tig];
            unsigned al2 = sAlo[(r0 + g) * 36 + k8 + tig + 4];
            unsigned al3 = sAlo[(r0 + g + 8) * 36 + k8 + tig + 4];
            #pragma unroll
            for (int nt = 0; nt < 4; nt++) {
                int n = wn * 32 + nt * 8;
                unsigned bh0 = sWhi[(k8 + tig) * 68 + n + g];
                unsigned bh1 = sWhi[(k8 + tig + 4) * 68 + n + g];
                unsigned bl0 = sWlo[(k8 + tig) * 68 + n + g];
                unsigned bl1 = sWlo[(k8 + tig + 4) * 68 + n + g];
                mma8(c[nt], ah0, ah1, ah2, ah3, bh0, bh1);   // hi*hi
                mma8(c[nt], ah0, ah1, ah2, ah3, bl0, bl1);   // hi*lo
                mma8(c[nt], al0, al1, al2, al3, bh0, bh1);   // lo*hi
            }
        }
    }
    #pragma unroll
    for (int nt = 0; nt < 4; nt++) {
        int cc = bn + wn * 32 + nt * 8 + 2 * tig;
        int r  = bm + wm * 16 + g;
        float b0v = bias[cc], b1v = bias[cc + 1];
        float v00 = c[nt][0] + b0v, v01 = c[nt][1] + b1v;
        float v10 = c[nt][2] + b0v, v11 = c[nt][3] + b1v;
        if (relu) {
            v00 = fmaxf(v00, 0.f); v01 = fmaxf(v01, 0.f);
            v10 = fmaxf(v10, 0.f); v11 = fmaxf(v11, 0.f);
        }
        *(float2*)&C[(size_t)r * DM + cc]       = make_float2(v00, v01);
        *(float2*)&C[(size_t)(r + 8) * DM + cc] = make_float2(v10, v11);
    }
}

// ---------------------------------------------------------------------------
// QK precompute: g_qk[h,i,j] = sum_d q[i,h,d]*k[j,h,d]  (raw, unscaled)
// ---------------------------------------------------------------------------
#define QK_SMEM (2 * 128 * 68 * 4)
__global__ void __launch_bounds__(256) qk_mma()
{
    extern __shared__ unsigned sm[];
    unsigned* sQ = sm;
    unsigned* sK = sm + 128 * 68;
    const int t = threadIdx.x, lane = t & 31, w = t >> 5;
    const int g = lane >> 2, tig = lane & 3;
    const int h = blockIdx.z, i0 = blockIdx.y * 128, j0 = blockIdx.x * 128;

    #pragma unroll
    for (int u = 0; u < 8; u++) {
        int f4 = t + 256 * u;
        int row = f4 >> 4;
        int c4 = (f4 & 15) * 4;
        float4 qv = *(const float4*)&g_q[(size_t)(i0 + row) * DM + h * DK + c4];
        unsigned* dq = sQ + row * 68 + c4;
        dq[0] = f2tf(qv.x); dq[1] = f2tf(qv.y); dq[2] = f2tf(qv.z); dq[3] = f2tf(qv.w);
        float4 kv = *(const float4*)&g_k[(size_t)(j0 + row) * DM + h * DK + c4];
        unsigned* dk = sK + row * 68 + c4;
        dk[0] = f2tf(kv.x); dk[1] = f2tf(kv.y); dk[2] = f2tf(kv.z); dk[3] = f2tf(kv.w);
    }
    __syncthreads();

    float c[16][4] = {};
    #pragma unroll
    for (int k0 = 0; k0 < 64; k0 += 8) {
        unsigned a0 = sQ[(16 * w + g) * 68 + k0 + tig];
        unsigned a1 = sQ[(16 * w + g + 8) * 68 + k0 + tig];
        unsigned a2 = sQ[(16 * w + g) * 68 + k0 + tig + 4];
        unsigned a3 = sQ[(16 * w + g + 8) * 68 + k0 + tig + 4];
        #pragma unroll
        for (int nt = 0; nt < 16; nt++) {
            unsigned b0 = sK[(8 * nt + g) * 68 + k0 + tig];
            unsigned b1 = sK[(8 * nt + g) * 68 + k0 + tig + 4];
            mma8(c[nt], a0, a1, a2, a3, b0, b1);
        }
    }
    size_t base = ((size_t)h << 20);
    #pragma unroll
    for (int nt = 0; nt < 16; nt++) {
        int jj = j0 + 8 * nt + 2 * tig;
        int ii = i0 + 16 * w + g;
        *(float2*)&g_qk[base + (size_t)ii * NSEQ + jj] = make_float2(c[nt][0], c[nt][1]);
        *(float2*)&g_qk[base + (size_t)(ii + 8) * NSEQ + jj] = make_float2(c[nt][2], c[nt][3]);
    }
}

// ---------------------------------------------------------------------------
// edge_fused: one CTA per query row i; loops all 8 j-tiles. Per tile:
//   [128j x 64e] @ [64e x 128dd] tf32 MMA -> sk (smem, relu) | sv (-> g_sv bf16)
//   score MMA: sk[128x64] @ qT[64x8] -> g_qk[h,i,j] = (qk + q.sk)*0.125
// W/qT staged once; next S tile prefetched into registers during epilogue.
// smem words: sW 8704 | sE 8704 (reused as fp32 SV stage) | sSK 8704 | sQT 576 | sB 128
// ---------------------------------------------------------------------------
#define P2_SMEM ((8704 * 3 + 576 + 128) * 4)
__global__ void __launch_bounds__(256, 2) edge_fused(
    const float* __restrict__ S,
    const float* __restrict__ Wsk, const float* __restrict__ bsk,
    const float* __restrict__ Wsv, const float* __restrict__ bsv)
{
    extern __shared__ unsigned sm2[];
    unsigned* sW  = sm2;                 // [64][136]
    unsigned* sE  = sm2 + 8704;          // [128][68] tf32 E; later fp32 SV stage
    unsigned* sSK = sm2 + 17408;         // [128][68] tf32 sk
    unsigned* sQT = sm2 + 26112;         // [64][9]
    float*    sB  = (float*)(sm2 + 26688); // bsk[0:64) | bsv[64:128)
    float*    sSV = (float*)sE;

    const int t = threadIdx.x, lane = t & 31, w = t >> 5;
    const int g = lane >> 2, tig = lane & 3;
    const int i = blockIdx.x;
    const int mq = w & 3, ng = w >> 2;

    const float4* Srow = (const float4*)(S + (size_t)i * NSEQ * 64);

    // deep prefetch of tile 0
    float4 pre[8];
    #pragma unroll
    for (int u = 0; u < 8; u++) pre[u] = Srow[t + 256 * u];

    // stage W (Wsk|Wsv) as tf32, pitch 136 (once)
    #pragma unroll
    for (int u = 0; u < 8; u++) {
        int f4 = t + 256 * u;
        int e = f4 >> 5;
        int c4 = (f4 & 31) * 4;
        const float* src = (c4 < 64) ? (Wsk + e * 64 + c4) : (Wsv + e * 64 + c4 - 64);
        float4 v = *(const float4*)src;
        unsigned* dst = sW + e * 136 + c4;
        dst[0] = f2tf(v.x); dst[1] = f2tf(v.y); dst[2] = f2tf(v.z); dst[3] = f2tf(v.w);
    }
    // stage qT [d][h] (once)
    #pragma unroll
    for (int u = 0; u < 2; u++) {
        int idx = t + 256 * u;
        sQT[(idx & 63) * 9 + (idx >> 6)] = f2tf(g_q[(size_t)i * DM + idx]);
    }
    if (t < 128) sB[t] = (t < 64) ? bsk[t] : bsv[t - 64];

    for (int jt = 0; jt < 8; jt++) {
        const int j0 = jt * 128;
        // STS E tile from prefetch regs (tf32)
        #pragma unroll
        for (int u = 0; u < 8; u++) {
            int f4 = t + 256 * u;
            int j = f4 >> 4;
            int e4 = (f4 & 15) * 4;
            unsigned* dst = sE + j * 68 + e4;
            dst[0] = f2tf(pre[u].x); dst[1] = f2tf(pre[u].y);
            dst[2] = f2tf(pre[u].z); dst[3] = f2tf(pre[u].w);
        }
        __syncthreads();   // sE (and first iter: sW/sQT/sB) ready

        // GEMM1: warp = (mq -> 32 rows, ng -> 64 cols)
        float c[2][8][4] = {};
        #pragma unroll
        for (int k = 0; k < 8; k++) {
            int k0 = k * 8;
            unsigned a[2][4];
            #pragma unroll
            for (int mt = 0; mt < 2; mt++) {
                int r0 = mq * 32 + mt * 16;
                a[mt][0] = sE[(r0 + g) * 68 + k0 + tig];
                a[mt][1] = sE[(r0 + g + 8) * 68 + k0 + tig];
                a[mt][2] = sE[(r0 + g) * 68 + k0 + tig + 4];
                a[mt][3] = sE[(r0 + g + 8) * 68 + k0 + tig + 4];
            }
            #pragma unroll
            for (int nt = 0; nt < 8; nt++) {
                int dd = ng * 64 + nt * 8;
                unsigned b0 = sW[(k0 + tig) * 136 + dd + g];
                unsigned b1 = sW[(k0 + tig + 4) * 136 + dd + g];
                mma8(c[0][nt], a[0][0], a[0][1], a[0][2], a[0][3], b0, b1);
                mma8(c[1][nt], a[1][0], a[1][1], a[1][2], a[1][3], b0, b1);
            }
        }

        // ng==0 warps: sk = relu(c + bsk) -> sSK (tf32)
        if (ng == 0) {
            #pragma unroll
            for (int mt = 0; mt < 2; mt++) {
                int r0 = mq * 32 + mt * 16;
                #pragma unroll
                for (int nt = 0; nt < 8; nt++) {
                    int dd = nt * 8 + 2 * tig;
                    float b0v = sB[dd], b1v = sB[dd + 1];
                    sSK[(r0 + g) * 68 + dd]         = f2tf(fmaxf(c[mt][nt][0] + b0v, 0.f));
                    sSK[(r0 + g) * 68 + dd + 1]     = f2tf(fmaxf(c[mt][nt][1] + b1v, 0.f));
                    sSK[(r0 + g + 8) * 68 + dd]     = f2tf(fmaxf(c[mt][nt][2] + b0v, 0.f));
                    sSK[(r0 + g + 8) * 68 + dd + 1] = f2tf(fmaxf(c[mt][nt][3] + b1v, 0.f));
                }
            }
        }
        __syncthreads();   // sSK complete; sE reads done -> free for SV staging

        if (ng == 1) {
            #pragma unroll
            for (int mt = 0; mt < 2; mt++) {
                int r0 = mq * 32 + mt * 16;
                #pragma unroll
                for (int nt = 0; nt < 8; nt++) {
                    int dv = nt * 8 + 2 * tig;
                    float b0v = sB[64 + dv], b1v = sB[64 + dv + 1];
                    sSV[(r0 + g) * 68 + dv]         = c[mt][nt][0] + b0v;
                    sSV[(r0 + g) * 68 + dv + 1]     = c[mt][nt][1] + b1v;
                    sSV[(r0 + g + 8) * 68 + dv]     = c[mt][nt][2] + b0v;
                    sSV[(r0 + g + 8) * 68 + dv + 1] = c[mt][nt][3] + b1v;
                }
            }
        }

        // prefetch next tile (latency covered by score MMA + epilogue + SV write)
        if (jt < 7) {
            #pragma unroll
            for (int u = 0; u < 8; u++) pre[u] = Srow[(jt + 1) * 2048 + t + 256 * u];
        }

        // score MMA: s2[128j x 8h] = sk @ qT ; warp w = m16 tile
        float cs[4] = {};
        #pragma unroll
        for (int k = 0; k < 8; k++) {
            int k0 = k * 8;
            unsigned a0 = sSK[(16 * w + g) * 68 + k0 + tig];
            unsigned a1 = sSK[(16 * w + g + 8) * 68 + k0 + tig];
            unsigned a2 = sSK[(16 * w + g) * 68 + k0 + tig + 4];
            unsigned a3 = sSK[(16 * w + g + 8) * 68 + k0 + tig + 4];
            unsigned b0 = sQT[(k0 + tig) * 9 + g];
            unsigned b1 = sQT[(k0 + tig + 4) * 9 + g];
            mma8(cs, a0, a1, a2, a3, b0, b1);
        }
        {
            int h0 = 2 * tig;
            int jr = 16 * w + g;
            size_t ibase = ((size_t)i << 10) + j0;
            size_t p00 = ((size_t)h0 << 20) + ibase + jr;
            size_t p01 = ((size_t)(h0 + 1) << 20) + ibase + jr;
            g_qk[p00]     = (g_qk[p00]     + cs[0]) * 0.125f;
            g_qk[p01]     = (g_qk[p01]     + cs[1]) * 0.125f;
            g_qk[p00 + 8] = (g_qk[p00 + 8] + cs[2]) * 0.125f;
            g_qk[p01 + 8] = (g_qk[p01 + 8] + cs[3]) * 0.125f;
        }
        __syncthreads();   // sSV complete

        // cooperative SV write: fp32 smem -> bf16 gmem, coalesced
        #pragma unroll
        for (int u = 0; u < 4; u++) {
            int idx = t + 256 * u;
            int j = idx >> 3;
            int d0 = (idx & 7) * 8;
            const float* src = &sSV[j * 68 + d0];
            __nv_bfloat162 b0 = __float22bfloat162_rn(make_float2(src[0], src[1]));
            __nv_bfloat162 b1 = __float22bfloat162_rn(make_float2(src[2], src[3]));
            __nv_bfloat162 b2 = __float22bfloat162_rn(make_float2(src[4], src[5]));
            __nv_bfloat162 b3 = __float22bfloat162_rn(make_float2(src[6], src[7]));
            uint4 pkt;
            pkt.x = *(unsigned*)&b0; pkt.y = *(unsigned*)&b1;
            pkt.z = *(unsigned*)&b2; pkt.w = *(unsigned*)&b3;
            *(uint4*)((char*)g_sv + (((size_t)i << 10) + j0 + j) * 128 + d0 * 2) = pkt;
        }
        __syncthreads();   // sSV reads done before next iter's STS into sE
    }
}

// ---------------------------------------------------------------------------
// softmax over rows of g_qk (8192 rows of 1024), normalized, in place.
// ---------------------------------------------------------------------------
__global__ void __launch_bounds__(256) softmax_rows()
{
    __shared__ float rbuf[8];
    const int t = threadIdx.x, lane = t & 31, w = t >> 5;
    float4* row4 = (float4*)(g_qk + ((size_t)blockIdx.x << 10));
    float4 v = row4[t];

    float mx = fmaxf(fmaxf(v.x, v.y), fmaxf(v.z, v.w));
    #pragma unroll
    for (int o = 16; o > 0; o >>= 1) mx = fmaxf(mx, __shfl_xor_sync(0xffffffffu, mx, o));
    if (lane == 0) rbuf[w] = mx;
    __syncthreads();
    if (t < 32) {
        float z = (lane < 8) ? rbuf[lane] : -1e30f;
        #pragma unroll
        for (int o = 4; o > 0; o >>= 1) z = fmaxf(z, __shfl_xor_sync(0xffffffffu, z, o));
        if (lane == 0) rbuf[0] = z;
    }
    __syncthreads();
    float m = rbuf[0];
    __syncthreads();

    float4 e;
    e.x = __expf(v.x - m); e.y = __expf(v.y - m);
    e.z = __expf(v.z - m); e.w = __expf(v.w - m);
    float s = e.x + e.y + e.z + e.w;
    #pragma unroll
    for (int o = 16; o > 0; o >>= 1) s += __shfl_xor_sync(0xffffffffu, s, o);
    if (lane == 0) rbuf[w] = s;
    __syncthreads();
    if (t < 32) {
        float z = (lane < 8) ? rbuf[lane] : 0.f;
        #pragma unroll
        for (int o = 4; o > 0; o >>= 1) z += __shfl_xor_sync(0xffffffffu, z, o);
        if (lane == 0) rbuf[0] = z;
    }
    __syncthreads();
    float inv = 1.0f / rbuf[0];
    e.x *= inv; e.y *= inv; e.z *= inv; e.w *= inv;
    row4[t] = e;
}

// ---------------------------------------------------------------------------
// pv_gemm: PV[i, h*64+d] = sum_j p[h,i,j] * v[j, h*64+d]. grid (16 it, 8 h).
// ---------------------------------------------------------------------------
__global__ void __launch_bounds__(256) pv_gemm()
{
    __shared__ unsigned sP[64 * 68];
    __shared__ unsigned sV[64 * 68];
    const int t = threadIdx.x, lane = t & 31, w = t >> 5;
    const int g = lane >> 2, tig = lane & 3;
    const int i0 = blockIdx.x * 64, h = blockIdx.y;
    const int m = w & 3, nh = w >> 2;

    float c[4][4] = {};
    for (int j0 = 0; j0 < NSEQ; j0 += 64) {
        __syncthreads();
        #pragma unroll
        for (int u = 0; u < 4; u++) {
            int f4 = t + 256 * u;
            int r = f4 >> 4;
            int c4 = (f4 & 15) * 4;
            float4 pv = *(const float4*)&g_qk[((size_t)h << 20) + ((size_t)(i0 + r) << 10) + j0 + c4];
            unsigned* dp = sP + r * 68 + c4;
            dp[0] = f2tf(pv.x); dp[1] = f2tf(pv.y); dp[2] = f2tf(pv.z); dp[3] = f2tf(pv.w);
            float4 vv = *(const float4*)&g_v[(size_t)(j0 + r) * DM + h * DK + c4];
            unsigned* dv = sV + r * 68 + c4;
            dv[0] = f2tf(vv.x); dv[1] = f2tf(vv.y); dv[2] = f2tf(vv.z); dv[3] = f2tf(vv.w);
        }
        __syncthreads();
        #pragma unroll
        for (int k = 0; k < 8; k++) {
            int k0 = k * 8;
            unsigned a0 = sP[(m * 16 + g) * 68 + k0 + tig];
            unsigned a1 = sP[(m * 16 + g + 8) * 68 + k0 + tig];
            unsigned a2 = sP[(m * 16 + g) * 68 + k0 + tig + 4];
            unsigned a3 = sP[(m * 16 + g + 8) * 68 + k0 + tig + 4];
            #pragma unroll
            for (int nt = 0; nt < 4; nt++) {
                int d = nh * 32 + nt * 8;
                unsigned b0 = sV[(k0 + tig) * 68 + d + g];
                unsigned b1 = sV[(k0 + tig + 4) * 68 + d + g];
                mma8(c[nt], a0, a1, a2, a3, b0, b1);
            }
        }
    }
    #pragma unroll
    for (int nt = 0; nt < 4; nt++) {
        int d = h * 64 + nh * 32 + nt * 8 + 2 * tig;
        int r = i0 + m * 16 + g;
        *(float2*)&g_pv[(size_t)r * DM + d]       = make_float2(c[nt][0], c[nt][1]);
        *(float2*)&g_pv[(size_t)(r + 8) * DM + d] = make_float2(c[nt][2], c[nt][3]);
    }
}

// ---------------------------------------------------------------------------
// sv_agg (tf32 MMA): attn[i,h*64+d] = PV + sum_j p[h,i,j]*sv[i,j,d].
// Per i: [8h x 1024j] @ [1024j x 64d]. Heads on M-dim (rows 8-15 zeroed via
// a1=a3=0). B = sv tile [j][d] straight from gmem layout (bf16 -> fp32 exact,
// valid tf32). One CTA per i, warp w owns d-cols [8w, 8w+8).
// ---------------------------------------------------------------------------
__global__ void __launch_bounds__(256) sv_agg()
{
    __shared__ unsigned sSv[128 * 68];   // [j][d] tf32 (fp32 bits from bf16)
    __shared__ unsigned pHT[8 * 132];    // [h][j] tf32
    const int t = threadIdx.x, lane = t & 31, w = t >> 5;
    const int g = lane >> 2, tig = lane & 3;
    const int i = blockIdx.x;

    const unsigned* svrow = (const unsigned*)g_sv + ((size_t)i << 10) * 32;

    float c[4] = {};
    for (int j0 = 0; j0 < NSEQ; j0 += 128) {
        __syncthreads();
        // stage sv tile: bf16x2 -> 2 fp32 words (exact)
        #pragma unroll
        for (int u = 0; u < 16; u++) {
            int idx = t + 256 * u;             // 4096 words
            int j = idx >> 5, dp = idx & 31;
            __nv_bfloat162 b = *(const __nv_bfloat162*)&svrow[(size_t)(j0 + j) * 32 + dp];
            float2 f = __bfloat1622float2(b);
            unsigned* dst = sSv + j * 68 + 2 * dp;
            dst[0] = __float_as_uint(f.x);
            dst[1] = __float_as_uint(f.y);
        }
        // stage p^T tile: [h][j]
        #pragma unroll
        for (int u = 0; u < 4; u++) {
            int idx = t + 256 * u;             // 1024
            int h = idx >> 7, j = idx & 127;
            pHT[h * 132 + j] = f2tf(g_qk[((size_t)h << 20) + ((size_t)i << 10) + j0 + j]);
        }
        __syncthreads();
        #pragma unroll
        for (int k = 0; k < 16; k++) {
            int k0 = k * 8;
            unsigned a0 = pHT[g * 132 + k0 + tig];
            unsigned a2 = pHT[g * 132 + k0 + tig + 4];
            unsigned b0 = sSv[(k0 + tig) * 68 + w * 8 + g];
            unsigned b1 = sSv[(k0 + tig + 4) * 68 + w * 8 + g];
            mma8(c, a0, 0u, a2, 0u, b0, b1);
        }
    }
    // c0,c1 = (h=g, d=w*8+2tig{,+1}); rows 8-15 (c2,c3) discarded
    {
        int h = g, d = w * 8 + 2 * tig;
        size_t o = (size_t)i * DM + h * DK + d;
        float2 pv = *(const float2*)&g_pv[o];
        *(float2*)&g_attn[o] = make_float2(c[0] + pv.x, c[1] + pv.y);
    }
}

// ---------------------------------------------------------------------------
extern "C" void kernel_launch(void* const* d_in, const int* in_sizes, int n_in,
                              void* d_out, int out_size)
{
    const float* x   = (const float*)d_in[0];
    const float* S   = (const float*)d_in[1];
    const float* Wq  = (const float*)d_in[2];
    const float* bq  = (const float*)d_in[3];
    const float* Wk  = (const float*)d_in[4];
    const float* bk  = (const float*)d_in[5];
    const float* Wv  = (const float*)d_in[6];
    const float* bv  = (const float*)d_in[7];
    const float* Wo  = (const float*)d_in[8];
    const float* bo  = (const float*)d_in[9];
    const float* Wsk = (const float*)d_in[10];
    const float* bsk = (const float*)d_in[11];
    const float* Wsv = (const float*)d_in[12];
    const float* bsv = (const float*)d_in[13];
    float* out = (float*)d_out;

    float *qp, *kp, *vp, *ap;
    cudaGetSymbolAddress((void**)&qp, g_q);
    cudaGetSymbolAddress((void**)&kp, g_k);
    cudaGetSymbolAddress((void**)&vp, g_v);
    cudaGetSymbolAddress((void**)&ap, g_attn);

    cudaFuncSetAttribute(qk_mma, cudaFuncAttributeMaxDynamicSharedMemorySize, QK_SMEM);
    cudaFuncSetAttribute(edge_fused, cudaFuncAttributeMaxDynamicSharedMemorySize, P2_SMEM);

    dim3 pg(DM / 64, NSEQ / 64);
    proj_mma<<<pg, 256>>>(x, Wq, bq, qp, 1);
    proj_mma<<<pg, 256>>>(x, Wk, bk, kp, 1);
    proj_mma<<<pg, 256>>>(x, Wv, bv, vp, 0);

    qk_mma<<<dim3(8, 8, 8), 256, QK_SMEM>>>();

    edge_fused<<<NSEQ, 256, P2_SMEM>>>(S, Wsk, bsk, Wsv, bsv);

    softmax_rows<<<NH * NSEQ, 256>>>();

    pv_gemm<<<dim3(16, 8), 256>>>();

    sv_agg<<<NSEQ, 256>>>();

    proj_mma<<<pg, 256>>>(ap, Wo, bo, out, 0);
}